// round 10
// baseline (speedup 1.0000x reference)
#include <cuda_runtime.h>
#include <cuda_bf16.h>
#include <math.h>

#define HS 65536
#define TT 128          // 64 tensor cols + 64 ffma cols
#define FTT 128
#define TOUT 63489
#define NLAYER 20

__device__ float g_h[2][64 * HS];
__device__ float g_skip[64 * TOUT];
__device__ float g_w1t[NLAYER * 128 * 128];   // [l][k][m]
__device__ float g_w2t[NLAYER * 64 * 128];

// ---------------- helpers ----------------
__device__ __forceinline__ unsigned pack_hl(float x){
    __nv_bfloat16 h=__float2bfloat16(x);
    __nv_bfloat16 l=__float2bfloat16(x-__bfloat162float(h));
    return (unsigned)__bfloat16_as_ushort(h) | ((unsigned)__bfloat16_as_ushort(l)<<16);
}
__device__ __forceinline__ unsigned bf2pack(__nv_bfloat16 a, __nv_bfloat16 b){
    return (unsigned)__bfloat16_as_ushort(a) | ((unsigned)__bfloat16_as_ushort(b)<<16);
}
__device__ __forceinline__ void split2(float a, float b, unsigned& h, unsigned& l){
    __nv_bfloat16 ha=__float2bfloat16(a), hb=__float2bfloat16(b);
    h = bf2pack(ha,hb);
    l = bf2pack(__float2bfloat16(a-__bfloat162float(ha)), __float2bfloat16(b-__bfloat162float(hb)));
}
__device__ __forceinline__ void split4(float4 v, uint2& h, uint2& l){
    unsigned h0,l0,h1,l1;
    split2(v.x,v.y,h0,l0); split2(v.z,v.w,h1,l1);
    h.x=h0; h.y=h1; l.x=l0; l.y=l1;
}
__device__ __forceinline__ int addrA(int m,int k,int kt){
    int ln=((m&7)<<2)|((k>>1)&3);
    int w=(k&1)|(((m>>3)&1)<<1)|(((k>>3)&1)<<2);
    return ((((m>>4)*kt+(k>>4))<<8)+(ln<<3)+w);
}
__device__ __forceinline__ int addrB128(int k,int t){
    int ln=((t&7)<<2)|((k>>1)&3);
    int w=(k&1)|(((k>>3)&1)<<1);
    return ((((k>>4)*16+(t>>3))<<7)+(ln<<2)+w);
}
__device__ __forceinline__ void mma_bf(float* d, const unsigned* a, const unsigned* b){
    asm volatile("mma.sync.aligned.m16n8k16.row.col.f32.bf16.bf16.f32 "
        "{%0,%1,%2,%3},{%4,%5,%6,%7},{%8,%9},{%0,%1,%2,%3};\n"
        :"+f"(d[0]),"+f"(d[1]),"+f"(d[2]),"+f"(d[3])
        :"r"(a[0]),"r"(a[1]),"r"(a[2]),"r"(a[3]),"r"(b[0]),"r"(b[1]));
}
__device__ __forceinline__ void ldsm4t(unsigned a, unsigned* d){
    asm volatile("ldmatrix.sync.aligned.m8n8.x4.trans.shared.b16 {%0,%1,%2,%3},[%4];"
        :"=r"(d[0]),"=r"(d[1]),"=r"(d[2]),"=r"(d[3]):"r"(a));
}
__device__ __forceinline__ void loadA(const unsigned* s,int mt,int kc,int kt,int lane,unsigned* Ah,unsigned* Al){
    const uint4* p=(const uint4*)(s+(((mt*kt+kc)<<8)+(lane<<3)));
    uint4 q0=p[0],q1=p[1];
    Ah[0]=__byte_perm(q0.x,q0.y,0x5410); Al[0]=__byte_perm(q0.x,q0.y,0x7632);
    Ah[1]=__byte_perm(q0.z,q0.w,0x5410); Al[1]=__byte_perm(q0.z,q0.w,0x7632);
    Ah[2]=__byte_perm(q1.x,q1.y,0x5410); Al[2]=__byte_perm(q1.x,q1.y,0x7632);
    Ah[3]=__byte_perm(q1.z,q1.w,0x5410); Al[3]=__byte_perm(q1.z,q1.w,0x7632);
}
__device__ __forceinline__ void loadB128(const unsigned* s,int kc,int nt,int lane,unsigned* Bh,unsigned* Bl){
    uint4 q=*(const uint4*)(s+(((kc*16+nt)<<7)+(lane<<2)));
    Bh[0]=__byte_perm(q.x,q.y,0x5410); Bl[0]=__byte_perm(q.x,q.y,0x7632);
    Bh[1]=__byte_perm(q.z,q.w,0x5410); Bl[1]=__byte_perm(q.z,q.w,0x7632);
}
__device__ __forceinline__ float fast_tanh(float x){
    float e=__expf(-2.0f*fabsf(x)); return copysignf(__fdividef(1.0f-e,1.0f+e),x);
}
__device__ __forceinline__ float fast_sig(float x){ return __fdividef(1.0f,1.0f+__expf(-x)); }
#define BAR(id) asm volatile("bar.sync %0, 512;"::"r"(id):"memory")

// ---------------- init ----------------
__global__ void init_kernel(const float* __restrict__ in, const float* __restrict__ w0,
                            const float* __restrict__ b0,
                            const float* __restrict__ wf, const float* __restrict__ wg,
                            const float* __restrict__ wr, const float* __restrict__ ws){
    int st = gridDim.x*blockDim.x;
    int tid0 = blockIdx.x*blockDim.x+threadIdx.x;
    for (int i=tid0; i<64*HS; i+=st){
        int c=i>>16, t=i&(HS-1);
        g_h[0][i] = w0[c]*in[t] + b0[c];
    }
    for (int i=tid0; i<64*TOUT; i+=st) g_skip[i]=0.0f;
    for (int i=tid0; i<NLAYER*128*128; i+=st){
        int l=i>>14, r=i&16383, k=r>>7, m=r&127;
        int c=k&63, lr=k>>6;
        g_w1t[i] = (m<64)? wf[((l*64+m)*64+c)*2+lr] : wg[((l*64+(m-64))*64+c)*2+lr];
    }
    for (int i=tid0; i<NLAYER*64*128; i+=st){
        int l=i>>13, r=i&8191, k=r>>7, m=r&127;
        g_w2t[i] = (m<64)? wr[(l*64+m)*64+k] : ws[(l*64+(m-64))*64+k];
    }
}

// ---------------- hybrid layer: 1024 thr, 16 tensor + 16 ffma warps ----------------
#define XHB 98304
#define XLB 114688
#define ZHB 131072
#define ZLB 139264
#define FXB 147456
#define SM_LAYER 180224

__global__ void __launch_bounds__(1024,1) layer_kernel(
    const float* __restrict__ wf, const float* __restrict__ wg,
    const float* __restrict__ wr, const float* __restrict__ ws,
    const float* __restrict__ bf, const float* __restrict__ bg,
    const float* __restrict__ br, const float* __restrict__ bs,
    const float* __restrict__ w1t, const float* __restrict__ w2t,
    int inbuf, int W, int d, int skip_shift)
{
    extern __shared__ unsigned smem[];
    unsigned char* smb = (unsigned char*)smem;
    unsigned* sW1p = smem;
    unsigned* sW2p = smem + 16384;
    float*    sF   = (float*)(smb + XHB);     // 128x64 fp32, aliases X planes
    float*    fX   = (float*)(smb + FXB);     // 128x64 fp32

    const float* __restrict__ hin = g_h[inbuf];
    float* __restrict__ hout = g_h[1-inbuf];
    const int tid = threadIdx.x, lane = tid&31, warp = tid>>5;
    const int Wout = W - d;
    const int ntiles = (Wout + TT - 1) / TT;
    const bool dal = ((d & 3) == 0);

    if (warp < 16){
        for (int idx=tid; idx<128*128; idx+=512){
            int k=idx>>7, m=idx&127;
            int c=k&63, lr=k>>6;
            float v = (m<64)? wf[(m*64+c)*2+lr] : wg[((m-64)*64+c)*2+lr];
            sW1p[addrA(m,k,8)] = pack_hl(v);
        }
        for (int idx=tid; idx<128*64; idx+=512){
            int k=idx>>7, m=idx&127;
            float v = (m<64)? wr[m*64+k] : ws[(m-64)*64+k];
            sW2p[addrA(m,k,4)] = pack_hl(v);
        }
    }
    __syncthreads();

    if (warp < 16){
        // ===== TENSOR: cols [t0, t0+64) =====
        const int wm = warp>>1;
        const int n0 = (warp&1)*32;
        const int mat = lane>>3, r8 = lane&7;
        const int koffB = (mat&1)*8 + r8;
        const unsigned xh_s = (unsigned)__cvta_generic_to_shared(smb+XHB);
        const unsigned xl_s = (unsigned)__cvta_generic_to_shared(smb+XLB);
        const unsigned zh_s = (unsigned)__cvta_generic_to_shared(smb+ZHB);
        const unsigned zl_s = (unsigned)__cvta_generic_to_shared(smb+ZLB);
        unsigned bofs[2];
        #pragma unroll
        for (int g=0; g<2; g++){
            int tcg = (n0>>3) + g*2 + (mat>>1);
            bofs[g] = (unsigned)(koffB*128 + ((tcg ^ r8)<<4));
        }

        for (int tile=blockIdx.x; tile<ntiles; tile+=gridDim.x){
            const int t0 = tile*TT;
            const bool fullT = (t0 + 64 <= Wout);
            for (int idx=tid; idx<2048; idx+=512){
                int k=idx>>4, q=idx&15;
                int c=k&63, t=q*4;
                int lt = t0 + t;
                int off = (k>=64)? d : 0;
                float4 v;
                if (fullT && (off==0 || dal)){
                    v = *(const float4*)(hin + c*HS + lt + off);
                } else {
                    float tmp[4];
                    #pragma unroll
                    for (int j=0;j<4;j++){
                        int g2 = lt+j;
                        tmp[j] = (g2<Wout)? hin[c*HS+g2+off] : 0.0f;
                    }
                    v = make_float4(tmp[0],tmp[1],tmp[2],tmp[3]);
                }
                uint2 h,l; split4(v,h,l);
                int b = k*128 + (((q>>1) ^ (k&7))<<4) + (q&1)*8;
                *(uint2*)(smb+XHB+b)=h; *(uint2*)(smb+XLB+b)=l;
            }
            BAR(2);

            // GEMM1: M=128 (warp: 16 rows), N=32, K=128
            float acc[4][4];
            #pragma unroll
            for (int b=0;b<4;b++){acc[b][0]=acc[b][1]=acc[b][2]=acc[b][3]=0.f;}
            #pragma unroll
            for (int kc=0;kc<8;kc++){
                unsigned Ah[4],Al[4];
                loadA(sW1p,wm,kc,8,lane,Ah,Al);
                #pragma unroll
                for (int g=0; g<2; g++){
                    unsigned bh[4], bl[4];
                    ldsm4t(xh_s + kc*2048 + bofs[g], bh);
                    ldsm4t(xl_s + kc*2048 + bofs[g], bl);
                    #pragma unroll
                    for (int sub=0; sub<2; sub++){
                        int nt = g*2+sub;
                        mma_bf(acc[nt],Ah,bh+sub*2);
                        mma_bf(acc[nt],Ah,bl+sub*2);
                        mma_bf(acc[nt],Al,bh+sub*2);
                    }
                }
            }
            BAR(2);
            // activations -> sF
            #pragma unroll
            for (int nt=0;nt<4;nt++){
                int tb = n0+nt*8+((lane&3)<<1);
                #pragma unroll
                for (int r=0;r<4;r++){
                    int m = wm*16 + (lane>>2) + ((r&2)?8:0);
                    int t = tb + (r&1);
                    float v = acc[nt][r];
                    v = (m<64)? fast_tanh(v+bf[m]) : fast_sig(v+bg[m-64]);
                    sF[m*64+t] = v;
                }
            }
            BAR(2);
            // z = f*g -> Z planes
            for (int idx=tid; idx<1024; idx+=512){
                int c=idx>>4, q=idx&15, t=q*4;
                float4 v;
                v.x = sF[c*64+t+0]*sF[(c+64)*64+t+0];
                v.y = sF[c*64+t+1]*sF[(c+64)*64+t+1];
                v.z = sF[c*64+t+2]*sF[(c+64)*64+t+2];
                v.w = sF[c*64+t+3]*sF[(c+64)*64+t+3];
                uint2 h,l; split4(v,h,l);
                int b = c*128 + (((q>>1) ^ (c&7))<<4) + (q&1)*8;
                *(uint2*)(smb+ZHB+b)=h; *(uint2*)(smb+ZLB+b)=l;
            }
            BAR(2);

            // GEMM2: K=64
            float ac2[4][4];
            #pragma unroll
            for (int b=0;b<4;b++){ac2[b][0]=ac2[b][1]=ac2[b][2]=ac2[b][3]=0.f;}
            #pragma unroll
            for (int kc=0;kc<4;kc++){
                unsigned Ah[4],Al[4];
                loadA(sW2p,wm,kc,4,lane,Ah,Al);
                #pragma unroll
                for (int g=0; g<2; g++){
                    unsigned bh[4], bl[4];
                    ldsm4t(zh_s + kc*2048 + bofs[g], bh);
                    ldsm4t(zl_s + kc*2048 + bofs[g], bl);
                    #pragma unroll
                    for (int sub=0; sub<2; sub++){
                        int nt = g*2+sub;
                        mma_bf(ac2[nt],Ah,bh+sub*2);
                        mma_bf(ac2[nt],Ah,bl+sub*2);
                        mma_bf(ac2[nt],Al,bh+sub*2);
                    }
                }
            }
            // epilogue
            #pragma unroll
            for (int nt=0;nt<4;nt++){
                int tb = n0+nt*8+((lane&3)<<1);
                #pragma unroll
                for (int r=0;r<4;r++){
                    int m = wm*16 + (lane>>2) + ((r&2)?8:0);
                    int gt = t0 + tb + (r&1);
                    float v = ac2[nt][r];
                    if (m<64){
                        if (gt<Wout) hout[m*HS+gt] = v + br[m] + hin[m*HS+gt+d];
                    } else {
                        int gc = gt - skip_shift;
                        if (gt<Wout && gc>=0 && gc<TOUT)
                            g_skip[(m-64)*TOUT+gc] += v + bs[m-64];
                    }
                }
            }
            BAR(2);
        }
    } else {
        // ===== FFMA: cols [t0+64, t0+128), 4m x 4t (R7 form) =====
        const int ftid = tid - 512;
        const int tg = ftid & 15, mg = ftid >> 4;
        const int tb = tg*4, mb = mg*4;
        for (int tile=blockIdx.x; tile<ntiles; tile+=gridDim.x){
            const int t0f = tile*TT + 64;
            const bool fullF = (t0f + 64 <= Wout);
            for (int idx=ftid; idx<2048; idx+=512){
                int k=idx>>4, q=idx&15;
                int c=k&63, t=q*4;
                int lt = t0f + t;
                int off = (k>=64)? d : 0;
                float4 v;
                if (fullF && (off==0 || dal)){
                    v = *(const float4*)(hin + c*HS + lt + off);
                } else {
                    float tmp[4];
                    #pragma unroll
                    for (int j=0;j<4;j++){
                        int g2 = lt+j;
                        tmp[j] = (g2<Wout)? hin[c*HS+g2+off] : 0.0f;
                    }
                    v = make_float4(tmp[0],tmp[1],tmp[2],tmp[3]);
                }
                *(float4*)&fX[k*64+t] = v;
            }
            BAR(1);

            float acc[4][4];
            #pragma unroll
            for (int i=0;i<4;i++){acc[i][0]=acc[i][1]=acc[i][2]=acc[i][3]=0.f;}
            #pragma unroll 8
            for (int k=0;k<128;k++){
                float a[4], b[4];
                *(float4*)&a[0] = *(const float4*)(w1t + k*128 + mb);
                *(float4*)&b[0] = *(const float4*)&fX[k*64 + tb];
                #pragma unroll
                for (int i=0;i<4;i++)
                    #pragma unroll
                    for (int j=0;j<4;j++) acc[i][j] += a[i]*b[j];
            }
            BAR(1);
            #pragma unroll
            for (int i=0;i<4;i++){
                int m = mb+i;
                float bias = (m<64)? bf[m] : bg[m-64];
                #pragma unroll
                for (int j=0;j<4;j++){
                    float v = acc[i][j] + bias;
                    v = (m<64)? fast_tanh(v) : fast_sig(v);
                    fX[m*64 + tb + j] = v;
                }
            }
            BAR(1);
            for (int idx=ftid; idx<4096; idx+=512)
                fX[idx] = fX[idx]*fX[4096+idx];
            BAR(1);

            float ac2[4][4];
            #pragma unroll
            for (int i=0;i<4;i++){ac2[i][0]=ac2[i][1]=ac2[i][2]=ac2[i][3]=0.f;}
            #pragma unroll 8
            for (int k=0;k<64;k++){
                float a[4], b[4];
                *(float4*)&a[0] = *(const float4*)(w2t + k*128 + mb);
                *(float4*)&b[0] = *(const float4*)&fX[k*64 + tb];
                #pragma unroll
                for (int i=0;i<4;i++)
                    #pragma unroll
                    for (int j=0;j<4;j++) ac2[i][j] += a[i]*b[j];
            }
            if (mb < 64){
                #pragma unroll
                for (int i=0;i<4;i++){
                    int m = mb+i;
                    float bias = br[m];
                    #pragma unroll
                    for (int j=0;j<4;j++){
                        int gt = t0f + tb + j;
                        if (gt<Wout) hout[m*HS+gt] = ac2[i][j] + bias + hin[m*HS+gt+d];
                    }
                }
            } else {
                #pragma unroll
                for (int i=0;i<4;i++){
                    int s = mb-64+i;
                    float bias = bs[s];
                    #pragma unroll
                    for (int j=0;j<4;j++){
                        int gt = t0f + tb + j;
                        int gc = gt - skip_shift;
                        if (gt<Wout && gc>=0 && gc<TOUT)
                            g_skip[s*TOUT+gc] += ac2[i][j] + bias;
                    }
                }
            }
            BAR(1);
        }
    }
}

// ---------------- output head ----------------
#define SM_FINAL (36864*4)
__global__ void __launch_bounds__(512,1) final_kernel(
    const float* __restrict__ alpha,
    const float* __restrict__ w0p, const float* __restrict__ b0p,
    const float* __restrict__ w1p, const float* __restrict__ b1p,
    float* __restrict__ out)
{
    extern __shared__ unsigned fs[];
    unsigned* sW0=fs; unsigned* sW1=fs+4096; unsigned* sB0=fs+20480; unsigned* sB1=fs+28672;
    const int tid=threadIdx.x, lane=tid&31, wrp=tid>>5;
    const int wm=wrp>>2, n0=(wrp&3)*32;

    for (int i=tid;i<64*64;i+=512) sW0[addrA(i>>6,i&63,4)]=pack_hl(w0p[i]);
    for (int i=tid;i<256*64;i+=512) sW1[addrA(i>>6,i&63,4)]=pack_hl(w1p[i]);
    __syncthreads();

    const int nt_total=(TOUT+FTT-1)/FTT;
    for (int tile=blockIdx.x; tile<nt_total; tile+=gridDim.x){
        const int t0=tile*FTT;
        for (int i=tid;i<64*FTT;i+=512){
            int c=i>>7, t=i&(FTT-1), gt=t0+t;
            float v=(gt<TOUT)?g_skip[c*TOUT+gt]:0.0f;
            v=(v>0.f)?v:alpha[c]*v;
            sB0[addrB128(c,t)]=pack_hl(v);
        }
        __syncthreads();

        float a0[4][4];
        #pragma unroll
        for (int b=0;b<4;b++){a0[b][0]=a0[b][1]=a0[b][2]=a0[b][3]=0.f;}
        #pragma unroll
        for (int kc=0;kc<4;kc++){
            unsigned Ah[4],Al[4],Bh[4][2],Bl[4][2];
            loadA(sW0,wm,kc,4,lane,Ah,Al);
            #pragma unroll
            for (int nt=0;nt<4;nt++) loadB128(sB0,kc,(n0>>3)+nt,lane,Bh[nt],Bl[nt]);
            #pragma unroll
            for (int nt=0;nt<4;nt++){
                mma_bf(a0[nt],Ah,Bh[nt]); mma_bf(a0[nt],Ah,Bl[nt]); mma_bf(a0[nt],Al,Bh[nt]);
            }
        }
        #pragma unroll
        for (int nt=0;nt<4;nt++){
            int tb=n0+nt*8+((lane&3)<<1);
            #pragma unroll
            for (int r=0;r<4;r++){
                int m=wm*16+(lane>>2)+((r&2)?8:0);
                float v=a0[nt][r]+b0p[m];
                v=(v>0.f)?v:alpha[64+m]*v;
                sB1[addrB128(m,tb+(r&1))]=pack_hl(v);
            }
        }
        __syncthreads();

        float a1[4][4][4];
        #pragma unroll
        for (int a=0;a<4;a++)
            #pragma unroll
            for (int b=0;b<4;b++){a1[a][b][0]=a1[a][b][1]=a1[a][b][2]=a1[a][b][3]=0.f;}
        #pragma unroll
        for (int kc=0;kc<4;kc++){
            unsigned Ah[4][4],Al[4][4],Bh[4][2],Bl[4][2];
            #pragma unroll
            for (int mt=0;mt<4;mt++) loadA(sW1,wm*4+mt,kc,4,lane,Ah[mt],Al[mt]);
            #pragma unroll
            for (int nt=0;nt<4;nt++) loadB128(sB1,kc,(n0>>3)+nt,lane,Bh[nt],Bl[nt]);
            #pragma unroll
            for (int mt=0;mt<4;mt++)
                #pragma unroll
                for (int nt=0;nt<4;nt++){
                    mma_bf(a1[mt][nt],Ah[mt],Bh[nt]); mma_bf(a1[mt][nt],Ah[mt],Bl[nt]); mma_bf(a1[mt][nt],Al[mt],Bh[nt]);
                }
        }
        #pragma unroll
        for (int mt=0;mt<4;mt++){
            int mbq=wm*64+mt*16+(lane>>2);
            #pragma unroll
            for (int nt=0;nt<4;nt++){
                int tb=n0+nt*8+((lane&3)<<1);
                #pragma unroll
                for (int r=0;r<4;r++){
                    int m=mbq+((r&2)?8:0), gt=t0+tb+(r&1);
                    if (gt<TOUT) out[m*TOUT+gt]=a1[mt][nt][r]+b1p[m];
                }
            }
        }
        __syncthreads();
    }
}

// ---------------- launch ----------------
extern "C" void kernel_launch(void* const* d_in, const int* in_sizes, int n_in,
                              void* d_out, int out_size) {
    const float* input =(const float*)d_in[0];
    const float* w0    =(const float*)d_in[1];
    const float* b0    =(const float*)d_in[2];
    const float* wf    =(const float*)d_in[3];
    const float* bf    =(const float*)d_in[4];
    const float* wg    =(const float*)d_in[5];
    const float* bg    =(const float*)d_in[6];
    const float* wr    =(const float*)d_in[7];
    const float* br    =(const float*)d_in[8];
    const float* ws    =(const float*)d_in[9];
    const float* bs    =(const float*)d_in[10];
    const float* alpha =(const float*)d_in[11];
    const float* w_out0=(const float*)d_in[12];
    const float* b_out0=(const float*)d_in[13];
    const float* w_out1=(const float*)d_in[14];
    const float* b_out1=(const float*)d_in[15];

    cudaFuncSetAttribute(layer_kernel, cudaFuncAttributeMaxDynamicSharedMemorySize, SM_LAYER);
    cudaFuncSetAttribute(final_kernel, cudaFuncAttributeMaxDynamicSharedMemorySize, SM_FINAL);

    init_kernel<<<512,256>>>(input, w0, b0, wf, wg, wr, ws);

    float* w1t_base = nullptr; float* w2t_base = nullptr;
    cudaGetSymbolAddress((void**)&w1t_base, g_w1t);
    cudaGetSymbolAddress((void**)&w2t_base, g_w2t);

    int W = HS, offset = 2048, buf = 0;
    for (int i = 0; i < NLAYER; i++){
        int d = 1 << (i % 10);
        offset -= d;
        layer_kernel<<<148,1024,SM_LAYER>>>(
            wf + i*64*64*2, wg + i*64*64*2, wr + i*64*64, ws + i*64*64,
            bf + i*64, bg + i*64, br + i*64, bs + i*64,
            w1t_base + i*128*128, w2t_base + i*64*128,
            buf, W, d, offset - 1);
        W -= d; buf ^= 1;
    }
    final_kernel<<<148,512,SM_FINAL>>>(alpha, w_out0, b_out0, w_out1, b_out1, (float*)d_out);
}

// round 12
// speedup vs baseline: 1.3820x; 1.3820x over previous
#include <cuda_runtime.h>
#include <cuda_bf16.h>
#include <math.h>

#define HS 65536
#define TOUT 63489
#define NLAYER 20
#define FTT 128

__device__ __nv_bfloat16 g_hh[2*64*HS + 8192];
__device__ __nv_bfloat16 g_hl[2*64*HS + 8192];
__device__ float g_skip[64*TOUT];

__device__ __forceinline__ unsigned bf2pack(__nv_bfloat16 a, __nv_bfloat16 b){
    return (unsigned)__bfloat16_as_ushort(a) | ((unsigned)__bfloat16_as_ushort(b)<<16);
}
__device__ __forceinline__ void split2(float a, float b, unsigned& h, unsigned& l){
    __nv_bfloat16 ha=__float2bfloat16(a), hb=__float2bfloat16(b);
    h = bf2pack(ha,hb);
    l = bf2pack(__float2bfloat16(a-__bfloat162float(ha)), __float2bfloat16(b-__bfloat162float(hb)));
}
__device__ __forceinline__ float blo(unsigned u){ return __bfloat162float(__ushort_as_bfloat16((unsigned short)(u&0xffff))); }
__device__ __forceinline__ float bhi(unsigned u){ return __bfloat162float(__ushort_as_bfloat16((unsigned short)(u>>16))); }
__device__ __forceinline__ void ldsm4t(unsigned a, unsigned* d){
    asm volatile("ldmatrix.sync.aligned.m8n8.x4.trans.shared.b16 {%0,%1,%2,%3},[%4];"
        :"=r"(d[0]),"=r"(d[1]),"=r"(d[2]),"=r"(d[3]):"r"(a));
}
__device__ __forceinline__ void mma_bf(float* d, const unsigned* a, const unsigned* b){
    asm volatile("mma.sync.aligned.m16n8k16.row.col.f32.bf16.bf16.f32 "
        "{%0,%1,%2,%3},{%4,%5,%6,%7},{%8,%9},{%0,%1,%2,%3};\n"
        :"+f"(d[0]),"+f"(d[1]),"+f"(d[2]),"+f"(d[3])
        :"r"(a[0]),"r"(a[1]),"r"(a[2]),"r"(a[3]),"r"(b[0]),"r"(b[1]));
}

// ---------------- MUFU-free activations ----------------
__device__ __forceinline__ float exp2_fma(float y){
    float ft = y + 12582912.0f;                    // RN to integer
    int ii = __float_as_int(ft) - 0x4B400000;
    float fi = ft - 12582912.0f;
    float f = y - fi;                              // [-0.5, 0.5]
    float p = 1.3333558146e-3f;
    p = fmaf(p, f, 9.6181291794e-3f);
    p = fmaf(p, f, 5.5504108664e-2f);
    p = fmaf(p, f, 2.4022650695e-1f);
    p = fmaf(p, f, 6.9314718056e-1f);
    p = fmaf(p, f, 1.0f);
    float sc = __int_as_float((ii + 127) << 23);
    return p * sc;
}
// 1/d for d in (1, 2]: seed 24/17 - 8/17 d (max rel err 1/17), 2 Newton steps
__device__ __forceinline__ float rcp_12(float d){
    float r = fmaf(-0.470588235f, d, 1.411764706f);
    r = r * fmaf(-d, r, 2.0f);
    r = r * fmaf(-d, r, 2.0f);
    return r;
}
__device__ __forceinline__ float fast_tanh(float x){
    float a = fabsf(x);
    float t = fmaxf(a * -2.88539008f, -30.0f);
    float u = exp2_fma(t);                         // e^{-2|x|} in (0,1]
    float r = rcp_12(1.0f + u);
    float th = (1.0f - u) * r;
    return copysignf(th, x);
}
__device__ __forceinline__ float fast_sig(float x){
    float a = fabsf(x);
    float t = fmaxf(a * -1.44269504f, -30.0f);
    float u = exp2_fma(t);                         // e^{-|x|} in (0,1]
    float r = rcp_12(1.0f + u);
    return (x >= 0.0f) ? r : u * r;
}

__global__ void init_kernel(const float* __restrict__ in, const float* __restrict__ w0,
                            const float* __restrict__ b0){
    int st = gridDim.x*blockDim.x;
    for (int i = blockIdx.x*blockDim.x+threadIdx.x; i < 64*HS; i += st){
        float v = w0[i>>16]*in[i&(HS-1)] + b0[i>>16];
        __nv_bfloat16 h = __float2bfloat16(v);
        g_hh[i] = h; g_hl[i] = __float2bfloat16(v-__bfloat162float(h));
    }
    for (int i = blockIdx.x*blockDim.x+threadIdx.x; i < 64*TOUT; i += st) g_skip[i] = 0.0f;
}

// smem bytes: Xhi[0,64K) Xlo[64K,128K) W1hi[128K,160K) W1lo[160K,192K) W2hi[192K,208K) W2lo[208K,224K)
__global__ void __launch_bounds__(512,1) layer_kernel(
    const float* __restrict__ wf, const float* __restrict__ wg,
    const float* __restrict__ wr, const float* __restrict__ ws,
    const float* __restrict__ bfp, const float* __restrict__ bgp,
    const float* __restrict__ brp, const float* __restrict__ bsp,
    int inbuf, int W, int d, int skip_shift)
{
    extern __shared__ unsigned char smem[];
    unsigned char* sXh = smem;
    unsigned char* sXl = smem + 65536;
    unsigned* sW1h = (unsigned*)(smem+131072);
    unsigned* sW1l = (unsigned*)(smem+163840);
    unsigned* sW2h = (unsigned*)(smem+196608);
    unsigned* sW2l = (unsigned*)(smem+212992);
    const int tid=threadIdx.x, lane=tid&31, warp=tid>>5;
    const int tw = warp*16, tw3 = warp*2;

    const __nv_bfloat16* hinh = g_hh + (size_t)inbuf*(64*HS);
    const __nv_bfloat16* hinl = g_hl + (size_t)inbuf*(64*HS);
    __nv_bfloat16* houth = g_hh + (size_t)(1-inbuf)*(64*HS);
    __nv_bfloat16* houtl = g_hl + (size_t)(1-inbuf)*(64*HS);

    for (int idx=tid; idx<128*64; idx+=512){
        int m=idx&127, k0=(idx>>7)*2;
        int c0=k0&63, l0=k0>>6, c1=(k0+1)&63, l1=(k0+1)>>6;
        float v0 = (m<64)? wf[(m*64+c0)*2+l0] : wg[((m-64)*64+c0)*2+l0];
        float v1 = (m<64)? wf[(m*64+c1)*2+l1] : wg[((m-64)*64+c1)*2+l1];
        int ml=m&15, kl=k0&15;
        int r = ((ml>>3)&1) | (((kl>>3)&1)<<1);
        int w = (((m>>4)*8 + (k0>>4))<<7) + ((ml&7)*4 + ((kl>>1)&3))*4 + r;
        unsigned h,l; split2(v0,v1,h,l); sW1h[w]=h; sW1l[w]=l;
    }
    for (int idx=tid; idx<128*32; idx+=512){
        int m=idx&127, k0=(idx>>7)*2;
        float v0 = (m<64)? wr[m*64+k0]   : ws[(m-64)*64+k0];
        float v1 = (m<64)? wr[m*64+k0+1] : ws[(m-64)*64+k0+1];
        int ml=m&15, kl=k0&15;
        int r = ((ml>>3)&1) | (((kl>>3)&1)<<1);
        int w = (((m>>4)*4 + (k0>>4))<<7) + ((ml&7)*4 + ((kl>>1)&3))*4 + r;
        unsigned h,l; split2(v0,v1,h,l); sW2h[w]=h; sW2l[w]=l;
    }
    __syncthreads();

    const int mat=lane>>3, r8=lane&7;
    const int koff=(mat&1)*8 + r8;
    const unsigned bofs = (unsigned)(koff*512 + (((tw3+(mat>>1))^r8)<<4));
    const unsigned xh_s = (unsigned)__cvta_generic_to_shared(sXh);
    const unsigned xl_s = (unsigned)__cvta_generic_to_shared(sXl);

    const int Wout = W-d;
    const int ntiles = (Wout+255)>>8;
    const int sh=d&7, q=sh>>1, odd=sh&1;

    for (int tile=blockIdx.x; tile<ntiles; tile+=gridDim.x){
        const int t0 = tile<<8;
        __syncwarp();
        #pragma unroll
        for (int it=0; it<2; it++){
            int c = lane + 32*it;
            size_t g = (size_t)c*HS + t0 + tw;
            int a0 = c*512 + (((tw3)^(c&7))<<4), a1 = c*512 + (((tw3+1)^(c&7))<<4);
            *(uint4*)(sXh+a0) = *(const uint4*)(hinh+g);
            *(uint4*)(sXh+a1) = *(const uint4*)(hinh+g+8);
            *(uint4*)(sXl+a0) = *(const uint4*)(hinl+g);
            *(uint4*)(sXl+a1) = *(const uint4*)(hinl+g+8);
            int k = 64+c;
            int b0a = k*512 + (((tw3)^(c&7))<<4), b1a = k*512 + (((tw3+1)^(c&7))<<4);
            if (sh==0){
                size_t gr = g + d;
                *(uint4*)(sXh+b0a) = *(const uint4*)(hinh+gr);
                *(uint4*)(sXh+b1a) = *(const uint4*)(hinh+gr+8);
                *(uint4*)(sXl+b0a) = *(const uint4*)(hinl+gr);
                *(uint4*)(sXl+b1a) = *(const uint4*)(hinl+gr+8);
            } else {
                size_t gr = g + (d - sh);
                unsigned wh[12], wl[12], oh[8], ol[8];
                *(uint4*)&wh[0]=*(const uint4*)(hinh+gr);   *(uint4*)&wh[4]=*(const uint4*)(hinh+gr+8);
                *(uint4*)&wh[8]=*(const uint4*)(hinh+gr+16);
                *(uint4*)&wl[0]=*(const uint4*)(hinl+gr);   *(uint4*)&wl[4]=*(const uint4*)(hinl+gr+8);
                *(uint4*)&wl[8]=*(const uint4*)(hinl+gr+16);
                #pragma unroll
                for (int i=0;i<8;i++){
                    int s=i+q;
                    oh[i] = odd ? __byte_perm(wh[s],wh[s+1],0x5432) : wh[s];
                    ol[i] = odd ? __byte_perm(wl[s],wl[s+1],0x5432) : wl[s];
                }
                *(uint4*)(sXh+b0a)=*(uint4*)&oh[0]; *(uint4*)(sXh+b1a)=*(uint4*)&oh[4];
                *(uint4*)(sXl+b0a)=*(uint4*)&ol[0]; *(uint4*)(sXl+b1a)=*(uint4*)&ol[4];
            }
        }
        __syncwarp();

        // GEMM1: M=128 N=16 K=128
        float acc[8][2][4];
        #pragma unroll
        for (int a=0;a<8;a++)
            #pragma unroll
            for (int b=0;b<2;b++){ acc[a][b][0]=acc[a][b][1]=acc[a][b][2]=acc[a][b][3]=0.f; }
        #pragma unroll
        for (int kc=0;kc<8;kc++){
            unsigned bh[4], bl[4];
            ldsm4t(xh_s + bofs + kc*8192, bh);
            ldsm4t(xl_s + bofs + kc*8192, bl);
            #pragma unroll
            for (int mt=0;mt<8;mt++){
                uint4 A = *(const uint4*)(sW1h + ((mt*8+kc)<<7) + (lane<<2));
                uint4 B = *(const uint4*)(sW1l + ((mt*8+kc)<<7) + (lane<<2));
                unsigned ah[4]={A.x,A.y,A.z,A.w}, al[4]={B.x,B.y,B.z,B.w};
                mma_bf(acc[mt][0],ah,bh);   mma_bf(acc[mt][1],ah,bh+2);
                mma_bf(acc[mt][0],ah,bl);   mma_bf(acc[mt][1],ah,bl+2);
                mma_bf(acc[mt][0],al,bh);   mma_bf(acc[mt][1],al,bh+2);
            }
        }
        // activations + z -> rows 0..63 of X planes
        #pragma unroll
        for (int mt=0;mt<4;mt++)
            #pragma unroll
            for (int rp=0;rp<2;rp++){
                int mr = mt*16 + (lane>>2) + rp*8;
                float bfv=bfp[mr], bgv=bgp[mr];
                #pragma unroll
                for (int nt=0;nt<2;nt++){
                    float z0 = fast_tanh(acc[mt][nt][rp*2+0]+bfv)*fast_sig(acc[mt+4][nt][rp*2+0]+bgv);
                    float z1 = fast_tanh(acc[mt][nt][rp*2+1]+bfv)*fast_sig(acc[mt+4][nt][rp*2+1]+bgv);
                    unsigned zh,zl; split2(z0,z1,zh,zl);
                    int ad = mr*512 + (((tw3+nt)^(mr&7))<<4) + ((lane&3)<<2);
                    *(unsigned*)(sXh+ad)=zh; *(unsigned*)(sXl+ad)=zl;
                }
            }
        __syncwarp();

        // GEMM2: M=128 N=16 K=64
        float ac2[8][2][4];
        #pragma unroll
        for (int a=0;a<8;a++)
            #pragma unroll
            for (int b=0;b<2;b++){ ac2[a][b][0]=ac2[a][b][1]=ac2[a][b][2]=ac2[a][b][3]=0.f; }
        #pragma unroll
        for (int kc=0;kc<4;kc++){
            unsigned bh[4], bl[4];
            ldsm4t(xh_s + bofs + kc*8192, bh);
            ldsm4t(xl_s + bofs + kc*8192, bl);
            #pragma unroll
            for (int mt=0;mt<8;mt++){
                uint4 A = *(const uint4*)(sW2h + ((mt*4+kc)<<7) + (lane<<2));
                uint4 B = *(const uint4*)(sW2l + ((mt*4+kc)<<7) + (lane<<2));
                unsigned ah[4]={A.x,A.y,A.z,A.w}, al[4]={B.x,B.y,B.z,B.w};
                mma_bf(ac2[mt][0],ah,bh);   mma_bf(ac2[mt][1],ah,bh+2);
                mma_bf(ac2[mt][0],ah,bl);   mma_bf(ac2[mt][1],ah,bl+2);
                mma_bf(ac2[mt][0],al,bh);   mma_bf(ac2[mt][1],al,bh+2);
            }
        }

        const bool full = (t0+256 <= Wout);
        #pragma unroll
        for (int mt=0;mt<4;mt++)
            #pragma unroll
            for (int rp=0;rp<2;rp++){
                int mr = mt*16 + (lane>>2) + rp*8;
                float bias = brp[mr];
                #pragma unroll
                for (int nt=0;nt<2;nt++){
                    int gt = t0 + tw + nt*8 + ((lane&3)<<1);
                    int ra = (64+mr)*512 + (((tw3+nt)^(mr&7))<<4) + ((lane&3)<<2);
                    unsigned rh=*(unsigned*)(sXh+ra), rl=*(unsigned*)(sXl+ra);
                    float v0 = ac2[mt][nt][rp*2+0] + bias + blo(rh) + blo(rl);
                    float v1 = ac2[mt][nt][rp*2+1] + bias + bhi(rh) + bhi(rl);
                    size_t go = (size_t)mr*HS + gt;
                    if (full){
                        unsigned oh,ol; split2(v0,v1,oh,ol);
                        *(unsigned*)(houth+go)=oh; *(unsigned*)(houtl+go)=ol;
                    } else {
                        if (gt < Wout){ __nv_bfloat16 h=__float2bfloat16(v0);
                            houth[go]=h; houtl[go]=__float2bfloat16(v0-__bfloat162float(h)); }
                        if (gt+1 < Wout){ __nv_bfloat16 h=__float2bfloat16(v1);
                            houth[go+1]=h; houtl[go+1]=__float2bfloat16(v1-__bfloat162float(h)); }
                    }
                }
            }
        #pragma unroll
        for (int mt=4;mt<8;mt++)
            #pragma unroll
            for (int rp=0;rp<2;rp++){
                int sr = (mt-4)*16 + (lane>>2) + rp*8;
                float bias = bsp[sr];
                #pragma unroll
                for (int nt=0;nt<2;nt++){
                    int gt = t0 + tw + nt*8 + ((lane&3)<<1);
                    #pragma unroll
                    for (int e=0;e<2;e++){
                        int gc = gt+e - skip_shift;
                        if (gt+e < Wout && gc >= 0 && gc < TOUT){
                            float* p = &g_skip[sr*TOUT+gc];
                            *p = *p + ac2[mt][nt][rp*2+e] + bias;
                        }
                    }
                }
            }
    }
}

// -------- output head --------
__device__ __forceinline__ unsigned pack_hl(float x){
    __nv_bfloat16 h=__float2bfloat16(x);
    __nv_bfloat16 l=__float2bfloat16(x-__bfloat162float(h));
    return (unsigned)__bfloat16_as_ushort(h) | ((unsigned)__bfloat16_as_ushort(l)<<16);
}
__device__ __forceinline__ int addrA(int m,int k,int kt){
    int ln=((m&7)<<2)|((k>>1)&3);
    int w=(k&1)|(((m>>3)&1)<<1)|(((k>>3)&1)<<2);
    return ((((m>>4)*kt+(k>>4))<<8)+(ln<<3)+w);
}
__device__ __forceinline__ int addrB(int k,int t){
    int ln=((t&7)<<2)|((k>>1)&3);
    int w=(k&1)|(((k>>3)&1)<<1);
    return ((((k>>4)*(FTT>>3)+(t>>3))<<7)+(ln<<2)+w);
}
__device__ __forceinline__ void loadA(const unsigned* s,int mt,int kc,int kt,int lane,unsigned* Ah,unsigned* Al){
    const uint4* p=(const uint4*)(s+(((mt*kt+kc)<<8)+(lane<<3)));
    uint4 q0=p[0],q1=p[1];
    Ah[0]=__byte_perm(q0.x,q0.y,0x5410); Al[0]=__byte_perm(q0.x,q0.y,0x7632);
    Ah[1]=__byte_perm(q0.z,q0.w,0x5410); Al[1]=__byte_perm(q0.z,q0.w,0x7632);
    Ah[2]=__byte_perm(q1.x,q1.y,0x5410); Al[2]=__byte_perm(q1.x,q1.y,0x7632);
    Ah[3]=__byte_perm(q1.z,q1.w,0x5410); Al[3]=__byte_perm(q1.z,q1.w,0x7632);
}
__device__ __forceinline__ void loadB(const unsigned* s,int kc,int nt,int lane,unsigned* Bh,unsigned* Bl){
    uint4 q=*(const uint4*)(s+(((kc*(FTT>>3)+nt)<<7)+(lane<<2)));
    Bh[0]=__byte_perm(q.x,q.y,0x5410); Bl[0]=__byte_perm(q.x,q.y,0x7632);
    Bh[1]=__byte_perm(q.z,q.w,0x5410); Bl[1]=__byte_perm(q.z,q.w,0x7632);
}

__global__ void __launch_bounds__(512,1) final_kernel(
    const float* __restrict__ alpha,
    const float* __restrict__ w0p, const float* __restrict__ b0p,
    const float* __restrict__ w1p, const float* __restrict__ b1p,
    float* __restrict__ out)
{
    extern __shared__ unsigned fs[];
    unsigned* sW0=fs; unsigned* sW1=fs+4096; unsigned* sB0=fs+20480; unsigned* sB1=fs+28672;
    const int tid=threadIdx.x, lane=tid&31, wrp=tid>>5;
    const int wm=wrp>>2, n0=(wrp&3)*32;

    for (int i=tid;i<64*64;i+=512) sW0[addrA(i>>6,i&63,4)]=pack_hl(w0p[i]);
    for (int i=tid;i<256*64;i+=512) sW1[addrA(i>>6,i&63,4)]=pack_hl(w1p[i]);
    __syncthreads();

    const int nt_total=(TOUT+FTT-1)/FTT;
    for (int tile=blockIdx.x; tile<nt_total; tile+=gridDim.x){
        const int t0=tile*FTT;
        for (int i=tid;i<64*FTT;i+=512){
            int c=i>>7, t=i&(FTT-1), gt=t0+t;
            float v=(gt<TOUT)?g_skip[c*TOUT+gt]:0.0f;
            v=(v>0.f)?v:alpha[c]*v;
            sB0[addrB(c,t)]=pack_hl(v);
        }
        __syncthreads();

        float a0[4][4];
        #pragma unroll
        for (int b=0;b<4;b++){ a0[b][0]=a0[b][1]=a0[b][2]=a0[b][3]=0.f; }
        #pragma unroll
        for (int kc=0;kc<4;kc++){
            unsigned Ah[4],Al[4],Bh[4][2],Bl[4][2];
            loadA(sW0,wm,kc,4,lane,Ah,Al);
            #pragma unroll
            for (int nt=0;nt<4;nt++) loadB(sB0,kc,(n0>>3)+nt,lane,Bh[nt],Bl[nt]);
            #pragma unroll
            for (int nt=0;nt<4;nt++){
                mma_bf(a0[nt],Ah,Bh[nt]); mma_bf(a0[nt],Ah,Bl[nt]); mma_bf(a0[nt],Al,Bh[nt]);
            }
        }
        #pragma unroll
        for (int nt=0;nt<4;nt++){
            int tb=n0+nt*8+((lane&3)<<1);
            #pragma unroll
            for (int r=0;r<4;r++){
                int m=wm*16+(lane>>2)+((r&2)?8:0);
                float v=a0[nt][r]+b0p[m];
                v=(v>0.f)?v:alpha[64+m]*v;
                sB1[addrB(m,tb+(r&1))]=pack_hl(v);
            }
        }
        __syncthreads();

        float a1[4][4][4];
        #pragma unroll
        for (int a=0;a<4;a++)
            #pragma unroll
            for (int b=0;b<4;b++){ a1[a][b][0]=a1[a][b][1]=a1[a][b][2]=a1[a][b][3]=0.f; }
        #pragma unroll
        for (int kc=0;kc<4;kc++){
            unsigned Ah[4][4],Al[4][4],Bh[4][2],Bl[4][2];
            #pragma unroll
            for (int mt=0;mt<4;mt++) loadA(sW1,wm*4+mt,kc,4,lane,Ah[mt],Al[mt]);
            #pragma unroll
            for (int nt=0;nt<4;nt++) loadB(sB1,kc,(n0>>3)+nt,lane,Bh[nt],Bl[nt]);
            #pragma unroll
            for (int mt=0;mt<4;mt++)
                #pragma unroll
                for (int nt=0;nt<4;nt++){
                    mma_bf(a1[mt][nt],Ah[mt],Bh[nt]); mma_bf(a1[mt][nt],Ah[mt],Bl[nt]); mma_bf(a1[mt][nt],Al[mt],Bh[nt]);
                }
        }
        #pragma unroll
        for (int mt=0;mt<4;mt++){
            int mb=wm*64+mt*16+(lane>>2);
            #pragma unroll
            for (int nt=0;nt<4;nt++){
                int tb=n0+nt*8+((lane&3)<<1);
                #pragma unroll
                for (int r=0;r<4;r++){
                    int m=mb+((r&2)?8:0), gt=t0+tb+(r&1);
                    if (gt<TOUT) out[m*TOUT+gt]=a1[mt][nt][r]+b1p[m];
                }
            }
        }
        __syncthreads();
    }
}

extern "C" void kernel_launch(void* const* d_in, const int* in_sizes, int n_in,
                              void* d_out, int out_size) {
    const float* input =(const float*)d_in[0];
    const float* w0    =(const float*)d_in[1];
    const float* b0    =(const float*)d_in[2];
    const float* wf    =(const float*)d_in[3];
    const float* bf    =(const float*)d_in[4];
    const float* wg    =(const float*)d_in[5];
    const float* bg    =(const float*)d_in[6];
    const float* wr    =(const float*)d_in[7];
    const float* br    =(const float*)d_in[8];
    const float* ws    =(const float*)d_in[9];
    const float* bs    =(const float*)d_in[10];
    const float* alpha =(const float*)d_in[11];
    const float* w_out0=(const float*)d_in[12];
    const float* b_out0=(const float*)d_in[13];
    const float* w_out1=(const float*)d_in[14];
    const float* b_out1=(const float*)d_in[15];

    const int SMEM_LAYER = 229376;
    const int SMEM_FINAL = 36864*4;
    cudaFuncSetAttribute(layer_kernel, cudaFuncAttributeMaxDynamicSharedMemorySize, SMEM_LAYER);
    cudaFuncSetAttribute(final_kernel, cudaFuncAttributeMaxDynamicSharedMemorySize, SMEM_FINAL);

    init_kernel<<<512,256>>>(input, w0, b0);

    int W = HS, offset = 2048, buf = 0;
    for (int i = 0; i < NLAYER; i++){
        int d = 1 << (i % 10);
        offset -= d;
        layer_kernel<<<148,512,SMEM_LAYER>>>(
            wf + i*64*64*2, wg + i*64*64*2, wr + i*64*64, ws + i*64*64,
            bf + i*64, bg + i*64, br + i*64, bs + i*64,
            buf, W, d, offset - 1);
        W -= d; buf ^= 1;
    }
    final_kernel<<<148,512,SMEM_FINAL>>>(alpha, w_out0, b_out0, w_out1, b_out1, (float*)d_out);
}